// round 1
// baseline (speedup 1.0000x reference)
#include <cuda_runtime.h>

#define HN 512
#define KN 64
#define NSAMP 16384
#define LRATE 0.001f
#define EPSF 1e-8f
#define WARPS 8
#define CHK 128
#define NCHUNK (HN/CHK)

// Precomputed scratch (allowed: __device__ globals, no allocation)
__device__ float g_BT[KN*HN];
__device__ float g_BdT[KN*HN];
__device__ float g_BddT[KN*HN];
__device__ float g_M[KN*KN];

__device__ __forceinline__ void f4u(float4 v, float* o) {
    o[0] = v.x; o[1] = v.y; o[2] = v.z; o[3] = v.w;
}

// K1: transpose B, B_dot, B_ddot -> (K,H) row-major
__global__ void transpose_kernel(const float* __restrict__ B,
                                 const float* __restrict__ Bd,
                                 const float* __restrict__ Bdd)
{
    int idx = blockIdx.x * blockDim.x + threadIdx.x;
    if (idx < KN*HN) {
        int k = idx >> 9;         // /512
        int h = idx & (HN-1);     // %512
        int src = h*KN + k;
        g_BT[idx]   = B[src];
        g_BdT[idx]  = Bd[src];
        g_BddT[idx] = Bdd[src];
    }
}

// K2: M = 2*(l1 * B^T B + l3 * Bddd^T Bddd)   (64x64)
__global__ void gram_kernel(const float* __restrict__ B,
                            const float* __restrict__ Bddd,
                            const float* __restrict__ lambdas)
{
    int k1 = blockIdx.x;
    int k2 = threadIdx.x;
    float accb = 0.f, accj = 0.f;
    for (int h = 0; h < HN; h++) {
        accb += B[h*KN + k1]    * B[h*KN + k2];
        accj += Bddd[h*KN + k1] * Bddd[h*KN + k2];
    }
    g_M[k1*KN + k2] = 2.f * (lambdas[0]*accb + lambdas[2]*accj);
}

// Elementwise gradient of the power-law (curvature) loss wrt V and A.
// Includes the l2 factor. g[0..2] = dL/dV, g[3..5] = dL/dA.
__device__ __forceinline__ void elemgrad(
    float v0, float v1, float v2,
    float a0, float a1, float a2,
    float aa, float bb, float l2, float* g)
{
    float vsq = v0*v0 + v1*v1 + v2*v2;
    float inv_vn = vsq > 0.f ? rsqrtf(vsq) : 0.f;
    float vn  = vsq * inv_vn;                 // ||V||
    float vne = vn + EPSF;

    float cx = v1*a2 - v2*a1;
    float cy = v2*a0 - v0*a2;
    float cz = v0*a1 - v1*a0;
    float csq = cx*cx + cy*cy + cz*cz;
    float inv_cn = csq > 0.f ? rsqrtf(csq) : 0.f;
    float cn = csq * inv_cn;                  // ||V x A||

    float den = vne*vne*vne + EPSF;
    float inv_den = __fdividef(1.f, den);
    float kappa = cn * inv_den;

    float ks  = fminf(fmaxf(kappa, 1e-4f), 1e4f);
    float lpr = bb * __logf(ks);
    float lp  = fminf(fmaxf(lpr, -10.f), 10.f);
    float traw   = aa * __expf(lp);
    float target = fminf(fmaxf(traw, 1e-6f), 1e6f);

    float u   = vn - target;
    float gvn = 2.f * l2 * u;                 // direct d/dvn
    float gt  = (traw > 1e-6f && traw < 1e6f) ? (-2.f * l2 * u) : 0.f;
    float glk = ((lpr > -10.f && lpr < 10.f) ? gt * traw : 0.f) * bb;
    float gk  = (kappa > 1e-4f && kappa < 1e4f) ? glk : 0.f;
    // simplified exact chain: g_cn = gk/cn ; g_den = -gk/den
    float gcn  = gk * inv_cn;
    float gden = -gk * inv_den;
    gvn += gden * 3.f * vne * vne;

    float scr = gcn * inv_cn;                 // g_cross = scr * cross
    float gc0 = scr * cx, gc1 = scr * cy, gc2 = scr * cz;
    float sV = gvn * inv_vn;
    // gV = sV*V + A x g_cross ; gA = g_cross x V
    g[0] = sV*v0 + a1*gc2 - a2*gc1;
    g[1] = sV*v1 + a2*gc0 - a0*gc2;
    g[2] = sV*v2 + a0*gc1 - a1*gc0;
    g[3] = gc1*v2 - gc2*v1;
    g[4] = gc2*v0 - gc0*v2;
    g[5] = gc0*v1 - gc1*v0;
}

// K3: main. One warp per sample; 8 samples per CTA.
__global__ __launch_bounds__(256, 2)
void inner_opt_kernel(const float* __restrict__ R_U,
                      const float* __restrict__ alpha,
                      const float* __restrict__ beta,
                      const float* __restrict__ lambdas,
                      const float* __restrict__ Bd,
                      const float* __restrict__ Bdd,
                      const float* __restrict__ Bpinv,
                      float* __restrict__ out)
{
    __shared__ __align__(16) float Csm[WARPS][KN*3];     // 6 KB
    __shared__ __align__(16) float gbuf[WARPS][6][CHK];  // 24 KB

    const int w = threadIdx.x >> 5;
    const int l = threadIdx.x & 31;
    const int s = blockIdx.x * WARPS + w;
    const int k0 = l, k1 = l + 32;

    const float l1 = lambdas[0], l2 = lambdas[1];
    const float aa = alpha[s], bbv = beta[s];

    // ---- init: C0 = Bpinv @ r ; wv = 2*l1 * B^T r ----
    float c[2][3]  = {{0,0,0},{0,0,0}};
    float wv[2][3] = {{0,0,0},{0,0,0}};
    {
        const float4* rp = (const float4*)(R_U + (size_t)s * (HN*3));
        const float4* p0 = (const float4*)(Bpinv + k0*HN);
        const float4* p1 = (const float4*)(Bpinv + k1*HN);
        const float4* t0 = (const float4*)(g_BT + k0*HN);
        const float4* t1 = (const float4*)(g_BT + k1*HN);
        #pragma unroll 4
        for (int q = 0; q < HN/4; q++) {
            float rr[12];
            f4u(rp[3*q+0], rr); f4u(rp[3*q+1], rr+4); f4u(rp[3*q+2], rr+8);
            float pa[4], pb[4], ta[4], tb[4];
            f4u(p0[q], pa); f4u(p1[q], pb); f4u(t0[q], ta); f4u(t1[q], tb);
            #pragma unroll
            for (int e = 0; e < 4; e++) {
                #pragma unroll
                for (int j = 0; j < 3; j++) {
                    float rv = rr[e*3+j];
                    c[0][j]  += pa[e]*rv;
                    c[1][j]  += pb[e]*rv;
                    wv[0][j] += ta[e]*rv;
                    wv[1][j] += tb[e]*rv;
                }
            }
        }
        #pragma unroll
        for (int j = 0; j < 3; j++) {
            wv[0][j] *= 2.f*l1; wv[1][j] *= 2.f*l1;
            Csm[w][k0*3+j] = c[0][j];
            Csm[w][k1*3+j] = c[1][j];
        }
    }
    __syncthreads();

    for (int step = 0; step < 3; step++) {
        float d[2][3] = {{0,0,0},{0,0,0}};
        for (int ch = 0; ch < NCHUNK; ch++) {
            const int base = ch * CHK;
            // ---- Phase A: forward V,A + elementwise grad -> gbuf ----
            #pragma unroll
            for (int t = 0; t < CHK/64; t++) {
                const int h0 = base + l + 64*t;
                const int h1 = h0 + 32;
                float V0[3]={0,0,0}, A0[3]={0,0,0};
                float V1[3]={0,0,0}, A1[3]={0,0,0};
                const float4* bd0 = (const float4*)(Bd  + h0*KN);
                const float4* bD0 = (const float4*)(Bdd + h0*KN);
                const float4* bd1 = (const float4*)(Bd  + h1*KN);
                const float4* bD1 = (const float4*)(Bdd + h1*KN);
                const float4* cp  = (const float4*)(Csm[w]);
                #pragma unroll 4
                for (int q = 0; q < 16; q++) {
                    float cv[12];
                    f4u(cp[3*q+0], cv); f4u(cp[3*q+1], cv+4); f4u(cp[3*q+2], cv+8);
                    float x0[4], y0[4], x1[4], y1[4];
                    f4u(bd0[q], x0); f4u(bD0[q], y0);
                    f4u(bd1[q], x1); f4u(bD1[q], y1);
                    #pragma unroll
                    for (int e = 0; e < 4; e++) {
                        #pragma unroll
                        for (int j = 0; j < 3; j++) {
                            float cj = cv[e*3+j];
                            V0[j] += x0[e]*cj;
                            A0[j] += y0[e]*cj;
                            V1[j] += x1[e]*cj;
                            A1[j] += y1[e]*cj;
                        }
                    }
                }
                float g[6];
                int hl = l + 64*t;
                elemgrad(V0[0],V0[1],V0[2], A0[0],A0[1],A0[2], aa,bbv,l2, g);
                #pragma unroll
                for (int p = 0; p < 6; p++) gbuf[w][p][hl] = g[p];
                elemgrad(V1[0],V1[1],V1[2], A1[0],A1[1],A1[2], aa,bbv,l2, g);
                #pragma unroll
                for (int p = 0; p < 6; p++) gbuf[w][p][hl+32] = g[p];
            }
            __syncthreads();
            // ---- Phase B: backward dC += Bd^T gV + Bdd^T gA (lane owns k0,k1) ----
            {
                const float4* td0 = (const float4*)(g_BdT  + k0*HN + base);
                const float4* td1 = (const float4*)(g_BdT  + k1*HN + base);
                const float4* tD0 = (const float4*)(g_BddT + k0*HN + base);
                const float4* tD1 = (const float4*)(g_BddT + k1*HN + base);
                #pragma unroll 4
                for (int q = 0; q < CHK/4; q++) {
                    float gp[6][4];
                    #pragma unroll
                    for (int p = 0; p < 6; p++)
                        f4u(((const float4*)gbuf[w][p])[q], gp[p]);
                    float u0[4], u1[4], z0[4], z1[4];
                    f4u(td0[q], u0); f4u(td1[q], u1);
                    f4u(tD0[q], z0); f4u(tD1[q], z1);
                    #pragma unroll
                    for (int e = 0; e < 4; e++) {
                        #pragma unroll
                        for (int j = 0; j < 3; j++) {
                            d[0][j] += u0[e]*gp[j][e] + z0[e]*gp[3+j][e];
                            d[1][j] += u1[e]*gp[j][e] + z1[e]*gp[3+j][e];
                        }
                    }
                }
            }
            __syncthreads();
        }
        // ---- Phase C: mc = M @ C, then SGD update ----
        float mc[2][3] = {{0,0,0},{0,0,0}};
        {
            const float4* m0 = (const float4*)(g_M + k0*KN);
            const float4* m1 = (const float4*)(g_M + k1*KN);
            const float4* cp = (const float4*)(Csm[w]);
            #pragma unroll 4
            for (int q = 0; q < 16; q++) {
                float cv[12];
                f4u(cp[3*q+0], cv); f4u(cp[3*q+1], cv+4); f4u(cp[3*q+2], cv+8);
                float ma[4], mb[4];
                f4u(m0[q], ma); f4u(m1[q], mb);
                #pragma unroll
                for (int e = 0; e < 4; e++) {
                    #pragma unroll
                    for (int j = 0; j < 3; j++) {
                        mc[0][j] += ma[e]*cv[e*3+j];
                        mc[1][j] += mb[e]*cv[e*3+j];
                    }
                }
            }
        }
        __syncthreads();   // all lanes done reading old C
        #pragma unroll
        for (int j = 0; j < 3; j++) {
            c[0][j] -= LRATE * (d[0][j] + mc[0][j] - wv[0][j]);
            c[1][j] -= LRATE * (d[1][j] + mc[1][j] - wv[1][j]);
            Csm[w][k0*3+j] = c[0][j];
            Csm[w][k1*3+j] = c[1][j];
        }
        __syncthreads();
    }

    float* op = out + (size_t)s * (KN*3);
    #pragma unroll
    for (int j = 0; j < 3; j++) {
        op[k0*3+j] = c[0][j];
        op[k1*3+j] = c[1][j];
    }
}

extern "C" void kernel_launch(void* const* d_in, const int* in_sizes, int n_in,
                              void* d_out, int out_size)
{
    const float* R_U     = (const float*)d_in[0];
    const float* alpha   = (const float*)d_in[1];
    const float* beta    = (const float*)d_in[2];
    const float* lambdas = (const float*)d_in[3];
    const float* B       = (const float*)d_in[4];
    const float* Bd      = (const float*)d_in[5];
    const float* Bdd     = (const float*)d_in[6];
    const float* Bddd    = (const float*)d_in[7];
    const float* Bpinv   = (const float*)d_in[8];

    transpose_kernel<<<(KN*HN + 255)/256, 256>>>(B, Bd, Bdd);
    gram_kernel<<<KN, KN>>>(B, Bddd, lambdas);
    inner_opt_kernel<<<NSAMP/WARPS, 256>>>(R_U, alpha, beta, lambdas,
                                           Bd, Bdd, Bpinv, (float*)d_out);
}

// round 2
// speedup vs baseline: 2.9615x; 2.9615x over previous
#include <cuda_runtime.h>

typedef unsigned long long ull;

#define HN 512
#define KN 64
#define NSAMP 16384
#define LRATE 0.001f
#define EPSF 1e-8f
#define WARPS 8
#define CHK 64
#define NCHUNK (HN/CHK)
#define FPAD (2*KN + 4)          // padded floats per staged row (132)

// smem layout (floats)
#define FS_FLOATS   (CHK*FPAD)                 // 8448
#define CS_OFF      FS_FLOATS                  // Cw: per warp 64 k * 4 float2 = 512 floats
#define GB_OFF      (CS_OFF + WARPS*512)       // Gw: per warp 3*64 float2 = 384 floats
#define SMEM_FLOATS (GB_OFF + WARPS*384)
#define SMEM_BYTES  (SMEM_FLOATS*4)

__device__ __align__(16) float  g_F2[HN*2*KN];   // [h][2k] = (Bd[h][k], Bdd[h][k])
__device__ __align__(16) float  g_BT[KN*HN];     // B^T
__device__ __align__(16) float2 g_Mp[KN*32];     // g_Mp[kk*32+l] = (M[kk][l], M[kk][l+32])

// ---- packed f32x2 helpers ----
__device__ __forceinline__ ull ffma2(ull a, ull b, ull c){
    ull d; asm("fma.rn.f32x2 %0,%1,%2,%3;" : "=l"(d) : "l"(a), "l"(b), "l"(c)); return d;
}
__device__ __forceinline__ void funpack(ull u, float& x, float& y){
    asm("mov.b64 {%0,%1},%2;" : "=f"(x), "=f"(y) : "l"(u));
}

// K1: interleave Bd/Bdd, transpose B
__global__ void prep_kernel(const float* __restrict__ B,
                            const float* __restrict__ Bd,
                            const float* __restrict__ Bdd)
{
    int idx = blockIdx.x * blockDim.x + threadIdx.x;
    if (idx < HN*KN) {
        int h = idx >> 6, k = idx & 63;
        g_F2[h*(2*KN) + 2*k]     = Bd[idx];
        g_F2[h*(2*KN) + 2*k + 1] = Bdd[idx];
        g_BT[k*HN + h]           = B[idx];
    }
}

// K2: M = 2*(l1*B^T B + l3*Bddd^T Bddd), stored pair-packed for lane reads
__global__ void gram_kernel(const float* __restrict__ B,
                            const float* __restrict__ Bddd,
                            const float* __restrict__ lambdas)
{
    __shared__ float Mrow[KN];
    int kk = blockIdx.x, k2 = threadIdx.x;
    float ab = 0.f, aj = 0.f;
    for (int h = 0; h < HN; h++) {
        ab += B[h*KN + kk]    * B[h*KN + k2];
        aj += Bddd[h*KN + kk] * Bddd[h*KN + k2];
    }
    Mrow[k2] = 2.f * (lambdas[0]*ab + lambdas[2]*aj);
    __syncthreads();
    if (k2 < 32) g_Mp[kk*32 + k2] = make_float2(Mrow[k2], Mrow[k2+32]);
}

// Elementwise gradient of the power-law term wrt V and A (includes l2).
__device__ __forceinline__ void elemgrad(
    float v0, float v1, float v2,
    float a0, float a1, float a2,
    float aa, float bb, float l2, float* g)
{
    float vsq = v0*v0 + v1*v1 + v2*v2;
    float inv_vn = vsq > 0.f ? rsqrtf(vsq) : 0.f;
    float vn  = vsq * inv_vn;
    float vne = vn + EPSF;

    float cx = v1*a2 - v2*a1;
    float cy = v2*a0 - v0*a2;
    float cz = v0*a1 - v1*a0;
    float csq = cx*cx + cy*cy + cz*cz;
    float inv_cn = csq > 0.f ? rsqrtf(csq) : 0.f;
    float cn = csq * inv_cn;

    float den = vne*vne*vne + EPSF;
    float inv_den = __fdividef(1.f, den);
    float kappa = cn * inv_den;

    float ks  = fminf(fmaxf(kappa, 1e-4f), 1e4f);
    float lpr = bb * __logf(ks);
    float lp  = fminf(fmaxf(lpr, -10.f), 10.f);
    float traw   = aa * __expf(lp);
    float target = fminf(fmaxf(traw, 1e-6f), 1e6f);

    float u   = vn - target;
    float gvn = 2.f * l2 * u;
    float gt  = (traw > 1e-6f && traw < 1e6f) ? (-2.f * l2 * u) : 0.f;
    float glk = ((lpr > -10.f && lpr < 10.f) ? gt * traw : 0.f) * bb;
    float gk  = (kappa > 1e-4f && kappa < 1e4f) ? glk : 0.f;
    float gcn  = gk * inv_cn;
    float gden = -gk * inv_den;
    gvn += gden * 3.f * vne * vne;

    float scr = gcn * inv_cn;
    float gc0 = scr * cx, gc1 = scr * cy, gc2 = scr * cz;
    float sV = gvn * inv_vn;
    g[0] = sV*v0 + a1*gc2 - a2*gc1;
    g[1] = sV*v1 + a2*gc0 - a0*gc2;
    g[2] = sV*v2 + a0*gc1 - a1*gc0;
    g[3] = gc1*v2 - gc2*v1;
    g[4] = gc2*v0 - gc0*v2;
    g[5] = gc0*v1 - gc1*v0;
}

// K3: main. One warp per sample; CTA stages B chunks in smem once for all 8 warps.
__global__ __launch_bounds__(256, 2)
void inner_opt_kernel(const float* __restrict__ R_U,
                      const float* __restrict__ alpha,
                      const float* __restrict__ beta,
                      const float* __restrict__ lambdas,
                      const float* __restrict__ Bpinv,
                      float* __restrict__ out)
{
    extern __shared__ __align__(16) float smem[];
    float*  Fs = smem;                                    // [CHK][FPAD]
    const int w = threadIdx.x >> 5;
    const int l = threadIdx.x & 31;
    float2* Cw = (float2*)(smem + CS_OFF) + w*256;        // [k][4] dup pairs
    float2* Gw = (float2*)(smem + GB_OFF) + w*192;        // [j][h] (gV,gA)

    const int s  = blockIdx.x * WARPS + w;
    const int k0 = l, k1 = l + 32;

    const float l1 = lambdas[0], l2 = lambdas[1];
    const float aa = alpha[s], bbv = beta[s];

    // ---- init: c = Bpinv @ r ; wv = 2*l1 * B^T r ----
    float c[2][3]  = {{0,0,0},{0,0,0}};
    float wv[2][3] = {{0,0,0},{0,0,0}};
    {
        const float4* rp = (const float4*)(R_U + (size_t)s * (HN*3));
        const float4* p0 = (const float4*)(Bpinv + k0*HN);
        const float4* p1 = (const float4*)(Bpinv + k1*HN);
        const float4* t0 = (const float4*)(g_BT + k0*HN);
        const float4* t1 = (const float4*)(g_BT + k1*HN);
        #pragma unroll 2
        for (int q = 0; q < HN/4; q++) {
            float4 r0 = rp[3*q+0], r1 = rp[3*q+1], r2 = rp[3*q+2];
            float rr[12] = {r0.x,r0.y,r0.z,r0.w, r1.x,r1.y,r1.z,r1.w, r2.x,r2.y,r2.z,r2.w};
            float4 pa = p0[q], pb = p1[q], ta = t0[q], tb = t1[q];
            float paf[4] = {pa.x,pa.y,pa.z,pa.w};
            float pbf[4] = {pb.x,pb.y,pb.z,pb.w};
            float taf[4] = {ta.x,ta.y,ta.z,ta.w};
            float tbf[4] = {tb.x,tb.y,tb.z,tb.w};
            #pragma unroll
            for (int e = 0; e < 4; e++)
                #pragma unroll
                for (int j = 0; j < 3; j++) {
                    float rv = rr[e*3+j];
                    c[0][j]  += paf[e]*rv;
                    c[1][j]  += pbf[e]*rv;
                    wv[0][j] += taf[e]*rv;
                    wv[1][j] += tbf[e]*rv;
                }
        }
        #pragma unroll
        for (int j = 0; j < 3; j++) { wv[0][j] *= 2.f*l1; wv[1][j] *= 2.f*l1; }
        // write duplicated-pair C
        #pragma unroll
        for (int j = 0; j < 3; j++) {
            Cw[k0*4+j] = make_float2(c[0][j], c[0][j]);
            Cw[k1*4+j] = make_float2(c[1][j], c[1][j]);
        }
        __syncwarp();
    }

    for (int step = 0; step < 3; step++) {
        ull acc[2][3] = {{0,0,0},{0,0,0}};   // packed (sum x*gV, sum y*gA) for k0,k1
        for (int ch = 0; ch < NCHUNK; ch++) {
            const int base = ch * CHK;
            // ---- stage F2 chunk into smem (all warps cooperate) ----
            __syncthreads();   // previous chunk fully consumed
            {
                const float4* src = (const float4*)(g_F2 + base*(2*KN));
                int t = threadIdx.x;
                #pragma unroll
                for (int i = 0; i < (CHK*2*KN/4)/256; i++) {
                    int idx = t + 256*i;
                    int h = idx >> 5, q = idx & 31;
                    ((float4*)(Fs + h*FPAD))[q] = src[h*32 + q];
                }
            }
            __syncthreads();

            // ---- Phase A: forward (V,A) + elementwise grad -> Gw ----
            {
                const ulonglong2* f0 = (const ulonglong2*)(Fs + l*FPAD);
                const ulonglong2* f1 = (const ulonglong2*)(Fs + (l+32)*FPAD);
                const ulonglong2* cp = (const ulonglong2*)Cw;
                ull va0[3] = {0,0,0}, va1[3] = {0,0,0};
                #pragma unroll 2
                for (int kp = 0; kp < 32; kp++) {
                    ulonglong2 cA0 = cp[4*kp+0];   // (c0,c0),(c1,c1) for k=2kp
                    ulonglong2 cA1 = cp[4*kp+1];   // (c2,c2),pad
                    ulonglong2 cB0 = cp[4*kp+2];   // k=2kp+1
                    ulonglong2 cB1 = cp[4*kp+3];
                    ulonglong2 x0 = f0[kp];        // (x,y) at k, k+1 for row l
                    ulonglong2 x1 = f1[kp];        // row l+32
                    va0[0] = ffma2(x0.x, cA0.x, va0[0]);
                    va0[1] = ffma2(x0.x, cA0.y, va0[1]);
                    va0[2] = ffma2(x0.x, cA1.x, va0[2]);
                    va0[0] = ffma2(x0.y, cB0.x, va0[0]);
                    va0[1] = ffma2(x0.y, cB0.y, va0[1]);
                    va0[2] = ffma2(x0.y, cB1.x, va0[2]);
                    va1[0] = ffma2(x1.x, cA0.x, va1[0]);
                    va1[1] = ffma2(x1.x, cA0.y, va1[1]);
                    va1[2] = ffma2(x1.x, cA1.x, va1[2]);
                    va1[0] = ffma2(x1.y, cB0.x, va1[0]);
                    va1[1] = ffma2(x1.y, cB0.y, va1[1]);
                    va1[2] = ffma2(x1.y, cB1.x, va1[2]);
                }
                float V[3], A[3], g[6];
                funpack(va0[0], V[0], A[0]);
                funpack(va0[1], V[1], A[1]);
                funpack(va0[2], V[2], A[2]);
                elemgrad(V[0],V[1],V[2], A[0],A[1],A[2], aa,bbv,l2, g);
                #pragma unroll
                for (int j = 0; j < 3; j++) Gw[j*CHK + l] = make_float2(g[j], g[3+j]);
                funpack(va1[0], V[0], A[0]);
                funpack(va1[1], V[1], A[1]);
                funpack(va1[2], V[2], A[2]);
                elemgrad(V[0],V[1],V[2], A[0],A[1],A[2], aa,bbv,l2, g);
                #pragma unroll
                for (int j = 0; j < 3; j++) Gw[j*CHK + l + 32] = make_float2(g[j], g[3+j]);
            }
            __syncwarp();

            // ---- Phase B: dC accumulation, column reads of same Fs chunk ----
            {
                const ulonglong2* pgj0 = (const ulonglong2*)(Gw);
                const ulonglong2* pgj1 = (const ulonglong2*)(Gw + CHK);
                const ulonglong2* pgj2 = (const ulonglong2*)(Gw + 2*CHK);
                #pragma unroll 2
                for (int hp = 0; hp < 32; hp++) {
                    ulonglong2 pg0 = pgj0[hp];     // (gV0,gA0) for h, h+1
                    ulonglong2 pg1 = pgj1[hp];
                    ulonglong2 pg2 = pgj2[hp];
                    const ull* rowA = (const ull*)(Fs + (2*hp)*FPAD);
                    const ull* rowB = (const ull*)(Fs + (2*hp+1)*FPAD);
                    ull t00 = rowA[l], t01 = rowA[l+32];
                    ull t10 = rowB[l], t11 = rowB[l+32];
                    acc[0][0] = ffma2(t00, pg0.x, acc[0][0]);
                    acc[0][1] = ffma2(t00, pg1.x, acc[0][1]);
                    acc[0][2] = ffma2(t00, pg2.x, acc[0][2]);
                    acc[1][0] = ffma2(t01, pg0.x, acc[1][0]);
                    acc[1][1] = ffma2(t01, pg1.x, acc[1][1]);
                    acc[1][2] = ffma2(t01, pg2.x, acc[1][2]);
                    acc[0][0] = ffma2(t10, pg0.y, acc[0][0]);
                    acc[0][1] = ffma2(t10, pg1.y, acc[0][1]);
                    acc[0][2] = ffma2(t10, pg2.y, acc[0][2]);
                    acc[1][0] = ffma2(t11, pg0.y, acc[1][0]);
                    acc[1][1] = ffma2(t11, pg1.y, acc[1][1]);
                    acc[1][2] = ffma2(t11, pg2.y, acc[1][2]);
                }
            }
        }

        // ---- Phase C: mc = M @ C (packed over k0/k1), then SGD update ----
        ull mca[3] = {0,0,0};
        {
            const ulonglong2* cp = (const ulonglong2*)Cw;
            #pragma unroll 2
            for (int kk = 0; kk < KN; kk++) {
                float2 mpf = g_Mp[kk*32 + l];
                ull pm = *(ull*)&mpf;              // (M[kk][k0], M[kk][k1])
                ulonglong2 c01 = cp[2*kk];          // (c0,c0),(c1,c1)
                ulonglong2 c2p = cp[2*kk+1];        // (c2,c2),pad
                mca[0] = ffma2(pm, c01.x, mca[0]);
                mca[1] = ffma2(pm, c01.y, mca[1]);
                mca[2] = ffma2(pm, c2p.x, mca[2]);
            }
        }
        __syncwarp();   // everyone done reading Cw before update
        #pragma unroll
        for (int j = 0; j < 3; j++) {
            float dlo, dhi, m0, m1;
            funpack(acc[0][j], dlo, dhi);
            float d0 = dlo + dhi;
            funpack(acc[1][j], dlo, dhi);
            float d1 = dlo + dhi;
            funpack(mca[j], m0, m1);
            c[0][j] -= LRATE * (d0 + m0 - wv[0][j]);
            c[1][j] -= LRATE * (d1 + m1 - wv[1][j]);
            Cw[k0*4+j] = make_float2(c[0][j], c[0][j]);
            Cw[k1*4+j] = make_float2(c[1][j], c[1][j]);
        }
        __syncwarp();
    }

    float* op = out + (size_t)s * (KN*3);
    #pragma unroll
    for (int j = 0; j < 3; j++) {
        op[k0*3+j] = c[0][j];
        op[k1*3+j] = c[1][j];
    }
}

extern "C" void kernel_launch(void* const* d_in, const int* in_sizes, int n_in,
                              void* d_out, int out_size)
{
    const float* R_U     = (const float*)d_in[0];
    const float* alpha   = (const float*)d_in[1];
    const float* beta    = (const float*)d_in[2];
    const float* lambdas = (const float*)d_in[3];
    const float* B       = (const float*)d_in[4];
    const float* Bd      = (const float*)d_in[5];
    const float* Bdd     = (const float*)d_in[6];
    const float* Bddd    = (const float*)d_in[7];
    const float* Bpinv   = (const float*)d_in[8];

    cudaFuncSetAttribute(inner_opt_kernel,
                         cudaFuncAttributeMaxDynamicSharedMemorySize, SMEM_BYTES);

    prep_kernel<<<(HN*KN + 255)/256, 256>>>(B, Bd, Bdd);
    gram_kernel<<<KN, KN>>>(B, Bddd, lambdas);
    inner_opt_kernel<<<NSAMP/WARPS, 256, SMEM_BYTES>>>(
        R_U, alpha, beta, lambdas, Bpinv, (float*)d_out);
}

// round 3
// speedup vs baseline: 4.3927x; 1.4832x over previous
#include <cuda_runtime.h>

typedef unsigned long long ull;

#define HN 512
#define KN 64
#define NSAMP 16384
#define LRATE 0.001f
#define EPSF 1e-8f
#define WARPS 8
#define CHK 64
#define NCHUNK (HN/CHK)
#define FPAD (2*KN + 4)          // 132 floats per staged row; 132 mod 32 = 4 -> conflict-free

// smem layout (floats)
#define FS_FLOATS   (CHK*FPAD)                   // 8448
#define CS_OFF      FS_FLOATS                    // Cw: warp x 2 samples x 512 floats
#define GB_OFF      (CS_OFF + WARPS*1024)        // Gw: warp x 2 samples x 384 floats
#define WV_OFF      (GB_OFF + WARPS*768)         // wv stash: warp x 32 lanes x 12 floats
#define SMEM_FLOATS (WV_OFF + WARPS*384)
#define SMEM_BYTES  (SMEM_FLOATS*4)

__device__ __align__(16) float  g_F2[HN*2*KN];   // [h][2k] = (Bd, Bdd)
__device__ __align__(16) float  g_PT[KN*2*HN];   // [k][2h] = (Bpinv[k][h], B[h][k])
__device__ __align__(16) float2 g_Mp[KN*32];     // [kk*32+l] = (M[kk][l], M[kk][l+32])

// ---- packed f32x2 helpers ----
__device__ __forceinline__ ull ffma2(ull a, ull b, ull c){
    ull d; asm("fma.rn.f32x2 %0,%1,%2,%3;" : "=l"(d) : "l"(a), "l"(b), "l"(c)); return d;
}
__device__ __forceinline__ void funpack(ull u, float& x, float& y){
    asm("mov.b64 {%0,%1},%2;" : "=f"(x), "=f"(y) : "l"(u));
}
__device__ __forceinline__ ull fdup(float x){
    ull r; asm("mov.b64 %0,{%1,%1};" : "=l"(r) : "f"(x)); return r;
}
__device__ __forceinline__ ull pack2(float lo, float hi){
    ull r; asm("mov.b64 %0,{%1,%2};" : "=l"(r) : "f"(lo), "f"(hi)); return r;
}

// K1: prep (blocks 0..127) + gram (blocks 128..191)
__global__ void prep_kernel(const float* __restrict__ B,
                            const float* __restrict__ Bd,
                            const float* __restrict__ Bdd,
                            const float* __restrict__ Bddd,
                            const float* __restrict__ Bpinv,
                            const float* __restrict__ lambdas)
{
    int bid = blockIdx.x, t = threadIdx.x;
    if (bid < 128) {
        int idx = bid*256 + t;
        // F2 interleave: idx -> (h,k)
        int h = idx >> 6, k = idx & 63;
        g_F2[h*(2*KN) + 2*k]     = Bd[idx];
        g_F2[h*(2*KN) + 2*k + 1] = Bdd[idx];
        // PT interleave: idx -> (k2,h2) over (K,H)
        int k2 = idx >> 9, h2 = idx & (HN-1);
        g_PT[k2*(2*HN) + 2*h2]     = Bpinv[idx];       // Bpinv is (K,H) row-major
        g_PT[k2*(2*HN) + 2*h2 + 1] = B[h2*KN + k2];
    } else {
        __shared__ float pab[4][KN], paj[4][KN], Mrow[KN];
        int kk = bid - 128;
        int k2 = t & 63, part = t >> 6;
        float ab = 0.f, aj = 0.f;
        for (int h = part*128; h < part*128 + 128; h++) {
            ab += B[h*KN + kk]    * B[h*KN + k2];
            aj += Bddd[h*KN + kk] * Bddd[h*KN + k2];
        }
        pab[part][k2] = ab; paj[part][k2] = aj;
        __syncthreads();
        if (t < KN) {
            float sab = pab[0][t]+pab[1][t]+pab[2][t]+pab[3][t];
            float saj = paj[0][t]+paj[1][t]+paj[2][t]+paj[3][t];
            Mrow[t] = 2.f * (lambdas[0]*sab + lambdas[2]*saj);
        }
        __syncthreads();
        if (t < 32) g_Mp[kk*32 + t] = make_float2(Mrow[t], Mrow[t+32]);
    }
}

// Elementwise gradient of the power-law term wrt V and A (includes l2).
__device__ __forceinline__ void elemgrad(
    float v0, float v1, float v2,
    float a0, float a1, float a2,
    float aa, float bb, float l2, float* g)
{
    float vsq = v0*v0 + v1*v1 + v2*v2;
    float inv_vn = vsq > 0.f ? rsqrtf(vsq) : 0.f;
    float vn  = vsq * inv_vn;
    float vne = vn + EPSF;

    float cx = v1*a2 - v2*a1;
    float cy = v2*a0 - v0*a2;
    float cz = v0*a1 - v1*a0;
    float csq = cx*cx + cy*cy + cz*cz;
    float inv_cn = csq > 0.f ? rsqrtf(csq) : 0.f;
    float cn = csq * inv_cn;

    float den = vne*vne*vne + EPSF;
    float inv_den = __fdividef(1.f, den);
    float kappa = cn * inv_den;

    float ks  = fminf(fmaxf(kappa, 1e-4f), 1e4f);
    float lpr = bb * __logf(ks);
    float lp  = fminf(fmaxf(lpr, -10.f), 10.f);
    float traw   = aa * __expf(lp);
    float target = fminf(fmaxf(traw, 1e-6f), 1e6f);

    float u   = vn - target;
    float gvn = 2.f * l2 * u;
    float gt  = (traw > 1e-6f && traw < 1e6f) ? (-2.f * l2 * u) : 0.f;
    float glk = ((lpr > -10.f && lpr < 10.f) ? gt * traw : 0.f) * bb;
    float gk  = (kappa > 1e-4f && kappa < 1e4f) ? glk : 0.f;
    float gcn  = gk * inv_cn;
    float gden = -gk * inv_den;
    gvn += gden * 3.f * vne * vne;

    float scr = gcn * inv_cn;
    float gc0 = scr * cx, gc1 = scr * cy, gc2 = scr * cz;
    float sV = gvn * inv_vn;
    g[0] = sV*v0 + a1*gc2 - a2*gc1;
    g[1] = sV*v1 + a2*gc0 - a0*gc2;
    g[2] = sV*v2 + a0*gc1 - a1*gc0;
    g[3] = gc1*v2 - gc2*v1;
    g[4] = gc2*v0 - gc0*v2;
    g[5] = gc0*v1 - gc1*v0;
}

// K2: main. One warp handles TWO samples; CTA stages F chunks for all 8 warps.
__global__ __launch_bounds__(256, 2)
void inner_opt_kernel(const float* __restrict__ R_U,
                      const float* __restrict__ alpha,
                      const float* __restrict__ beta,
                      const float* __restrict__ lambdas,
                      float* __restrict__ out)
{
    extern __shared__ __align__(16) float smem[];
    float* Fs = smem;                                           // [CHK][FPAD]
    const int w = threadIdx.x >> 5;
    const int l = threadIdx.x & 31;
    float2* CwA = (float2*)(smem + CS_OFF + w*1024);            // sample A: [k][4] dup pairs
    float2* CwB = CwA + 256;                                    // sample B
    float2* GwA = (float2*)(smem + GB_OFF + w*768);             // [j][h] (gV,gA)
    float2* GwB = GwA + 192;
    float*  Ws  = smem + WV_OFF + w*384;                        // [lane][12] -wv stash

    const int sA = blockIdx.x * (WARPS*2) + w*2;
    const int sB = sA + 1;
    const int k0 = l, k1 = l + 32;

    const float l1 = lambdas[0], l2 = lambdas[1];
    const float aaA = alpha[sA], bbA = beta[sA];
    const float aaB = alpha[sB], bbB = beta[sB];

    // ---- init: (c, wv_raw) pair-packed over interleaved PT ----
    {
        ull accw[2][2][3] = {{{0,0,0},{0,0,0}},{{0,0,0},{0,0,0}}};
        const ulonglong2* pt0 = (const ulonglong2*)(g_PT + k0*(2*HN));
        const ulonglong2* pt1 = (const ulonglong2*)(g_PT + k1*(2*HN));
        const float4* rpA = (const float4*)(R_U + (size_t)sA * (HN*3));
        const float4* rpB = (const float4*)(R_U + (size_t)sB * (HN*3));
        #pragma unroll 1
        for (int q = 0; q < HN/4; q++) {
            ulonglong2 pA0 = pt0[2*q], pA1 = pt0[2*q+1];
            ulonglong2 pB0 = pt1[2*q], pB1 = pt1[2*q+1];
            #pragma unroll
            for (int s = 0; s < 2; s++) {
                const float4* rp = s ? rpB : rpA;
                float4 r0 = rp[3*q], r1 = rp[3*q+1], r2 = rp[3*q+2];
                ull d0[3] = {fdup(r0.x), fdup(r0.y), fdup(r0.z)};
                ull d1[3] = {fdup(r0.w), fdup(r1.x), fdup(r1.y)};
                ull d2[3] = {fdup(r1.z), fdup(r1.w), fdup(r2.x)};
                ull d3[3] = {fdup(r2.y), fdup(r2.z), fdup(r2.w)};
                #pragma unroll
                for (int j = 0; j < 3; j++) {
                    accw[s][0][j] = ffma2(pA0.x, d0[j], accw[s][0][j]);
                    accw[s][0][j] = ffma2(pA0.y, d1[j], accw[s][0][j]);
                    accw[s][0][j] = ffma2(pA1.x, d2[j], accw[s][0][j]);
                    accw[s][0][j] = ffma2(pA1.y, d3[j], accw[s][0][j]);
                    accw[s][1][j] = ffma2(pB0.x, d0[j], accw[s][1][j]);
                    accw[s][1][j] = ffma2(pB0.y, d1[j], accw[s][1][j]);
                    accw[s][1][j] = ffma2(pB1.x, d2[j], accw[s][1][j]);
                    accw[s][1][j] = ffma2(pB1.y, d3[j], accw[s][1][j]);
                }
            }
        }
        #pragma unroll
        for (int s = 0; s < 2; s++) {
            float2* Cw = s ? CwB : CwA;
            #pragma unroll
            for (int k = 0; k < 2; k++) {
                int kidx = k ? k1 : k0;
                #pragma unroll
                for (int j = 0; j < 3; j++) {
                    float cv, wvr;
                    funpack(accw[s][k][j], cv, wvr);
                    Cw[kidx*4 + j] = make_float2(cv, cv);
                    Ws[l*12 + s*6 + k*3 + j] = -2.f*l1*wvr;   // folded into step acc init
                }
            }
        }
        __syncwarp();
    }

    for (int step = 0; step < 3; step++) {
        ull acc[2][2][3];   // packed (sum x*gV, sum y*gA); lo initialized to -wv
        #pragma unroll
        for (int s = 0; s < 2; s++)
            #pragma unroll
            for (int k = 0; k < 2; k++)
                #pragma unroll
                for (int j = 0; j < 3; j++)
                    acc[s][k][j] = pack2(Ws[l*12 + s*6 + k*3 + j], 0.f);

        for (int ch = 0; ch < NCHUNK; ch++) {
            const int base = ch * CHK;
            __syncthreads();   // previous chunk fully consumed by all warps
            {  // stage F2 chunk into smem (whole CTA cooperates)
                const float4* src = (const float4*)(g_F2 + base*(2*KN));
                int t = threadIdx.x;
                #pragma unroll
                for (int i = 0; i < (CHK*2*KN/4)/256; i++) {
                    int idx = t + 256*i;
                    int h = idx >> 5, q = idx & 31;
                    ((float4*)(Fs + h*FPAD))[q] = src[h*32 + q];
                }
            }
            __syncthreads();

            // ---- Phase A: forward (V,A) for 2 samples + elementwise grads ----
            {
                const ulonglong2* f0 = (const ulonglong2*)(Fs + l*FPAD);
                const ulonglong2* f1 = (const ulonglong2*)(Fs + (l+32)*FPAD);
                const ulonglong2* cpA = (const ulonglong2*)CwA;
                const ulonglong2* cpB = (const ulonglong2*)CwB;
                ull va[2][2][3] = {{{0,0,0},{0,0,0}},{{0,0,0},{0,0,0}}};
                #pragma unroll 2
                for (int kp = 0; kp < 32; kp++) {
                    ulonglong2 x0 = f0[kp], x1 = f1[kp];   // rows shared by both samples
                    ulonglong2 a0 = cpA[4*kp+0], a1 = cpA[4*kp+1];
                    ulonglong2 a2 = cpA[4*kp+2], a3 = cpA[4*kp+3];
                    va[0][0][0] = ffma2(x0.x, a0.x, va[0][0][0]);
                    va[0][0][1] = ffma2(x0.x, a0.y, va[0][0][1]);
                    va[0][0][2] = ffma2(x0.x, a1.x, va[0][0][2]);
                    va[0][0][0] = ffma2(x0.y, a2.x, va[0][0][0]);
                    va[0][0][1] = ffma2(x0.y, a2.y, va[0][0][1]);
                    va[0][0][2] = ffma2(x0.y, a3.x, va[0][0][2]);
                    va[0][1][0] = ffma2(x1.x, a0.x, va[0][1][0]);
                    va[0][1][1] = ffma2(x1.x, a0.y, va[0][1][1]);
                    va[0][1][2] = ffma2(x1.x, a1.x, va[0][1][2]);
                    va[0][1][0] = ffma2(x1.y, a2.x, va[0][1][0]);
                    va[0][1][1] = ffma2(x1.y, a2.y, va[0][1][1]);
                    va[0][1][2] = ffma2(x1.y, a3.x, va[0][1][2]);
                    ulonglong2 b0 = cpB[4*kp+0], b1 = cpB[4*kp+1];
                    ulonglong2 b2 = cpB[4*kp+2], b3 = cpB[4*kp+3];
                    va[1][0][0] = ffma2(x0.x, b0.x, va[1][0][0]);
                    va[1][0][1] = ffma2(x0.x, b0.y, va[1][0][1]);
                    va[1][0][2] = ffma2(x0.x, b1.x, va[1][0][2]);
                    va[1][0][0] = ffma2(x0.y, b2.x, va[1][0][0]);
                    va[1][0][1] = ffma2(x0.y, b2.y, va[1][0][1]);
                    va[1][0][2] = ffma2(x0.y, b3.x, va[1][0][2]);
                    va[1][1][0] = ffma2(x1.x, b0.x, va[1][1][0]);
                    va[1][1][1] = ffma2(x1.x, b0.y, va[1][1][1]);
                    va[1][1][2] = ffma2(x1.x, b1.x, va[1][1][2]);
                    va[1][1][0] = ffma2(x1.y, b2.x, va[1][1][0]);
                    va[1][1][1] = ffma2(x1.y, b2.y, va[1][1][1]);
                    va[1][1][2] = ffma2(x1.y, b3.x, va[1][1][2]);
                }
                float V[3], A[3], g[6];
                #pragma unroll
                for (int s = 0; s < 2; s++) {
                    float2* Gw = s ? GwB : GwA;
                    float aa = s ? aaB : aaA;
                    float bb = s ? bbB : bbA;
                    #pragma unroll
                    for (int r = 0; r < 2; r++) {
                        funpack(va[s][r][0], V[0], A[0]);
                        funpack(va[s][r][1], V[1], A[1]);
                        funpack(va[s][r][2], V[2], A[2]);
                        elemgrad(V[0],V[1],V[2], A[0],A[1],A[2], aa,bb,l2, g);
                        int hh = l + 32*r;
                        #pragma unroll
                        for (int j = 0; j < 3; j++)
                            Gw[j*CHK + hh] = make_float2(g[j], g[3+j]);
                    }
                }
            }
            __syncwarp();

            // ---- Phase B: dC accumulation for 2 samples (rows shared) ----
            {
                const ulonglong2* pgA0 = (const ulonglong2*)(GwA);
                const ulonglong2* pgA1 = (const ulonglong2*)(GwA + CHK);
                const ulonglong2* pgA2 = (const ulonglong2*)(GwA + 2*CHK);
                const ulonglong2* pgB0 = (const ulonglong2*)(GwB);
                const ulonglong2* pgB1 = (const ulonglong2*)(GwB + CHK);
                const ulonglong2* pgB2 = (const ulonglong2*)(GwB + 2*CHK);
                #pragma unroll 2
                for (int hp = 0; hp < 32; hp++) {
                    const ull* rowA = (const ull*)(Fs + (2*hp)*FPAD);
                    const ull* rowB = (const ull*)(Fs + (2*hp+1)*FPAD);
                    ull t00 = rowA[l], t01 = rowA[l+32];
                    ull t10 = rowB[l], t11 = rowB[l+32];
                    ulonglong2 p0 = pgA0[hp], p1 = pgA1[hp], p2 = pgA2[hp];
                    acc[0][0][0] = ffma2(t00, p0.x, acc[0][0][0]);
                    acc[0][0][1] = ffma2(t00, p1.x, acc[0][0][1]);
                    acc[0][0][2] = ffma2(t00, p2.x, acc[0][0][2]);
                    acc[0][1][0] = ffma2(t01, p0.x, acc[0][1][0]);
                    acc[0][1][1] = ffma2(t01, p1.x, acc[0][1][1]);
                    acc[0][1][2] = ffma2(t01, p2.x, acc[0][1][2]);
                    acc[0][0][0] = ffma2(t10, p0.y, acc[0][0][0]);
                    acc[0][0][1] = ffma2(t10, p1.y, acc[0][0][1]);
                    acc[0][0][2] = ffma2(t10, p2.y, acc[0][0][2]);
                    acc[0][1][0] = ffma2(t11, p0.y, acc[0][1][0]);
                    acc[0][1][1] = ffma2(t11, p1.y, acc[0][1][1]);
                    acc[0][1][2] = ffma2(t11, p2.y, acc[0][1][2]);
                    ulonglong2 q0 = pgB0[hp], q1 = pgB1[hp], q2 = pgB2[hp];
                    acc[1][0][0] = ffma2(t00, q0.x, acc[1][0][0]);
                    acc[1][0][1] = ffma2(t00, q1.x, acc[1][0][1]);
                    acc[1][0][2] = ffma2(t00, q2.x, acc[1][0][2]);
                    acc[1][1][0] = ffma2(t01, q0.x, acc[1][1][0]);
                    acc[1][1][1] = ffma2(t01, q1.x, acc[1][1][1]);
                    acc[1][1][2] = ffma2(t01, q2.x, acc[1][1][2]);
                    acc[1][0][0] = ffma2(t10, q0.y, acc[1][0][0]);
                    acc[1][0][1] = ffma2(t10, q1.y, acc[1][0][1]);
                    acc[1][0][2] = ffma2(t10, q2.y, acc[1][0][2]);
                    acc[1][1][0] = ffma2(t11, q0.y, acc[1][1][0]);
                    acc[1][1][1] = ffma2(t11, q1.y, acc[1][1][1]);
                    acc[1][1][2] = ffma2(t11, q2.y, acc[1][1][2]);
                }
            }
        }

        // ---- Phase C: mc = M @ C for both samples, then SGD update ----
        ull mca[2][3] = {{0,0,0},{0,0,0}};
        {
            const ulonglong2* cpA = (const ulonglong2*)CwA;
            const ulonglong2* cpB = (const ulonglong2*)CwB;
            #pragma unroll 2
            for (int kk = 0; kk < KN; kk++) {
                ull pm = *(const ull*)&g_Mp[kk*32 + l];   // (M[kk][k0], M[kk][k1])
                ulonglong2 ca = cpA[2*kk];
                ull ca2 = ((const ull*)cpA)[4*kk+2];
                mca[0][0] = ffma2(pm, ca.x, mca[0][0]);
                mca[0][1] = ffma2(pm, ca.y, mca[0][1]);
                mca[0][2] = ffma2(pm, ca2,  mca[0][2]);
                ulonglong2 cb = cpB[2*kk];
                ull cb2 = ((const ull*)cpB)[4*kk+2];
                mca[1][0] = ffma2(pm, cb.x, mca[1][0]);
                mca[1][1] = ffma2(pm, cb.y, mca[1][1]);
                mca[1][2] = ffma2(pm, cb2,  mca[1][2]);
            }
        }
        __syncwarp();   // all lanes done reading Cw before update
        #pragma unroll
        for (int s = 0; s < 2; s++) {
            float2* Cw = s ? CwB : CwA;
            #pragma unroll
            for (int k = 0; k < 2; k++) {
                int kidx = k ? k1 : k0;
                #pragma unroll
                for (int j = 0; j < 3; j++) {
                    float dlo, dhi, m0, m1;
                    funpack(acc[s][k][j], dlo, dhi);    // dlo includes -wv
                    funpack(mca[s][j], m0, m1);
                    float m = k ? m1 : m0;
                    float cold = Cw[kidx*4 + j].x;
                    float cn = cold - LRATE * (dlo + dhi + m);
                    Cw[kidx*4 + j] = make_float2(cn, cn);
                }
            }
        }
        __syncwarp();
    }

    // ---- output ----
    #pragma unroll
    for (int s = 0; s < 2; s++) {
        float* op = out + (size_t)(sA + s) * (KN*3);
        float2* Cw = s ? CwB : CwA;
        #pragma unroll
        for (int k = 0; k < 2; k++) {
            int kidx = k ? k1 : k0;
            #pragma unroll
            for (int j = 0; j < 3; j++)
                op[kidx*3 + j] = Cw[kidx*4 + j].x;
        }
    }
}

extern "C" void kernel_launch(void* const* d_in, const int* in_sizes, int n_in,
                              void* d_out, int out_size)
{
    const float* R_U     = (const float*)d_in[0];
    const float* alpha   = (const float*)d_in[1];
    const float* beta    = (const float*)d_in[2];
    const float* lambdas = (const float*)d_in[3];
    const float* B       = (const float*)d_in[4];
    const float* Bd      = (const float*)d_in[5];
    const float* Bdd     = (const float*)d_in[6];
    const float* Bddd    = (const float*)d_in[7];
    const float* Bpinv   = (const float*)d_in[8];

    cudaFuncSetAttribute(inner_opt_kernel,
                         cudaFuncAttributeMaxDynamicSharedMemorySize, SMEM_BYTES);

    prep_kernel<<<192, 256>>>(B, Bd, Bdd, Bddd, Bpinv, lambdas);
    inner_opt_kernel<<<NSAMP/(WARPS*2), 256, SMEM_BYTES>>>(
        R_U, alpha, beta, lambdas, (float*)d_out);
}

// round 4
// speedup vs baseline: 4.7449x; 1.0802x over previous
#include <cuda_runtime.h>
#include <cuda_bf16.h>

typedef unsigned long long ull;

#define HN 512
#define KN 64
#define NSAMP 16384
#define LRATE 0.001f
#define EPSF 1e-8f
#define WARPS 8
#define CHK 64
#define NCHUNK (HN/CHK)
#define FPAD (2*KN + 4)          // 132 floats per staged fp32 row (conflict-free rows)

// smem layout (floats)
#define FS_FLOATS   (CHK*FPAD)                   // 8448 (fp32 F chunk, Phase A)
#define FB_OFF      FS_FLOATS                    // bf16 F chunk: CHK*32 ull = 4096 floats
#define CS_OFF      (FB_OFF + 4096)              // C: warp x 2 samples x 256 floats
#define GB_OFF      (CS_OFF + WARPS*512)         // G: warp x 2 samples x 384 floats
#define WV_OFF      (GB_OFF + WARPS*768)         // wv stash: warp x 384 floats
#define SMEM_FLOATS (WV_OFF + WARPS*384)
#define SMEM_BYTES  (SMEM_FLOATS*4)              // 103424 B -> 2 CTAs/SM

__device__ __align__(16) float  g_F2[HN*2*KN];   // [h][2k] = (Bd, Bdd) fp32
__device__ __align__(16) ull    g_Fb[HN*32];     // [h][l]: bf16 (Bd,Bdd) for k=l and k=l+32
__device__ __align__(16) float  g_PT[KN*2*HN];   // [k][2h] = (Bpinv[k][h], B[h][k])
__device__ __align__(16) float2 g_Mp[KN*32];     // [kk*32+l] = (M[kk][l], M[kk][l+32])

// ---- packed f32x2 helpers ----
__device__ __forceinline__ ull ffma2(ull a, ull b, ull c){
    ull d; asm("fma.rn.f32x2 %0,%1,%2,%3;" : "=l"(d) : "l"(a), "l"(b), "l"(c)); return d;
}
__device__ __forceinline__ void funpack(ull u, float& x, float& y){
    asm("mov.b64 {%0,%1},%2;" : "=f"(x), "=f"(y) : "l"(u));
}
__device__ __forceinline__ ull fdup(float x){
    ull r; asm("mov.b64 %0,{%1,%1};" : "=l"(r) : "f"(x)); return r;
}
__device__ __forceinline__ ull pack2(float lo, float hi){
    ull r; asm("mov.b64 %0,{%1,%2};" : "=l"(r) : "f"(lo), "f"(hi)); return r;
}
// u32 holding (bf16 x in low16, bf16 y in high16) -> packed f32x2 (x, y)
__device__ __forceinline__ ull bf2f2(unsigned w){
    unsigned lo = w << 16;
    unsigned hi = w & 0xFFFF0000u;
    ull r; asm("mov.b64 %0,{%1,%2};" : "=l"(r) : "r"(lo), "r"(hi)); return r;
}

// K1: prep (blocks 0..127) + gram (blocks 128..191)
__global__ void prep_kernel(const float* __restrict__ B,
                            const float* __restrict__ Bd,
                            const float* __restrict__ Bdd,
                            const float* __restrict__ Bddd,
                            const float* __restrict__ Bpinv,
                            const float* __restrict__ lambdas)
{
    int bid = blockIdx.x, t = threadIdx.x;
    if (bid < 128) {
        int idx = bid*256 + t;
        // F2 interleave: idx -> (h,k)
        int h = idx >> 6, k = idx & 63;
        g_F2[h*(2*KN) + 2*k]     = Bd[idx];
        g_F2[h*(2*KN) + 2*k + 1] = Bdd[idx];
        // PT interleave: idx -> (k2,h2)
        int k2 = idx >> 9, h2 = idx & (HN-1);
        g_PT[k2*(2*HN) + 2*h2]     = Bpinv[idx];
        g_PT[k2*(2*HN) + 2*h2 + 1] = B[h2*KN + k2];
        // bf16 backward copy: idx2 -> (h,l), packs k=l and k=l+32
        if (idx < HN*32) {
            int hb = idx >> 5, lb = idx & 31;
            unsigned short x0 = __bfloat16_as_ushort(__float2bfloat16(Bd [hb*KN + lb]));
            unsigned short y0 = __bfloat16_as_ushort(__float2bfloat16(Bdd[hb*KN + lb]));
            unsigned short x1 = __bfloat16_as_ushort(__float2bfloat16(Bd [hb*KN + lb + 32]));
            unsigned short y1 = __bfloat16_as_ushort(__float2bfloat16(Bdd[hb*KN + lb + 32]));
            unsigned w0 = ((unsigned)y0 << 16) | x0;
            unsigned w1 = ((unsigned)y1 << 16) | x1;
            g_Fb[idx] = ((ull)w1 << 32) | w0;
        }
    } else {
        __shared__ float pab[4][KN], paj[4][KN], Mrow[KN];
        int kk = bid - 128;
        int k2 = t & 63, part = t >> 6;
        float ab = 0.f, aj = 0.f;
        for (int h = part*128; h < part*128 + 128; h++) {
            ab += B[h*KN + kk]    * B[h*KN + k2];
            aj += Bddd[h*KN + kk] * Bddd[h*KN + k2];
        }
        pab[part][k2] = ab; paj[part][k2] = aj;
        __syncthreads();
        if (t < KN) {
            float sab = pab[0][t]+pab[1][t]+pab[2][t]+pab[3][t];
            float saj = paj[0][t]+paj[1][t]+paj[2][t]+paj[3][t];
            Mrow[t] = 2.f * (lambdas[0]*sab + lambdas[2]*saj);
        }
        __syncthreads();
        if (t < 32) g_Mp[kk*32 + t] = make_float2(Mrow[t], Mrow[t+32]);
    }
}

// Elementwise gradient of the power-law term wrt V and A (includes l2).
__device__ __forceinline__ void elemgrad(
    float v0, float v1, float v2,
    float a0, float a1, float a2,
    float aa, float bb, float l2, float* g)
{
    float vsq = v0*v0 + v1*v1 + v2*v2;
    float inv_vn = vsq > 0.f ? rsqrtf(vsq) : 0.f;
    float vn  = vsq * inv_vn;
    float vne = vn + EPSF;

    float cx = v1*a2 - v2*a1;
    float cy = v2*a0 - v0*a2;
    float cz = v0*a1 - v1*a0;
    float csq = cx*cx + cy*cy + cz*cz;
    float inv_cn = csq > 0.f ? rsqrtf(csq) : 0.f;
    float cn = csq * inv_cn;

    float den = vne*vne*vne + EPSF;
    float inv_den = __fdividef(1.f, den);
    float kappa = cn * inv_den;

    float ks  = fminf(fmaxf(kappa, 1e-4f), 1e4f);
    float lpr = bb * __logf(ks);
    float lp  = fminf(fmaxf(lpr, -10.f), 10.f);
    float traw   = aa * __expf(lp);
    float target = fminf(fmaxf(traw, 1e-6f), 1e6f);

    float u   = vn - target;
    float gvn = 2.f * l2 * u;
    float gt  = (traw > 1e-6f && traw < 1e6f) ? (-2.f * l2 * u) : 0.f;
    float glk = ((lpr > -10.f && lpr < 10.f) ? gt * traw : 0.f) * bb;
    float gk  = (kappa > 1e-4f && kappa < 1e4f) ? glk : 0.f;
    float gcn  = gk * inv_cn;
    float gden = -gk * inv_den;
    gvn += gden * 3.f * vne * vne;

    float scr = gcn * inv_cn;
    float gc0 = scr * cx, gc1 = scr * cy, gc2 = scr * cz;
    float sV = gvn * inv_vn;
    g[0] = sV*v0 + a1*gc2 - a2*gc1;
    g[1] = sV*v1 + a2*gc0 - a0*gc2;
    g[2] = sV*v2 + a0*gc1 - a1*gc0;
    g[3] = gc1*v2 - gc2*v1;
    g[4] = gc2*v0 - gc0*v2;
    g[5] = gc0*v1 - gc1*v0;
}

// K2: main. One warp = 2 samples; fp32 F for forward, bf16 F for backward.
__global__ __launch_bounds__(256, 2)
void inner_opt_kernel(const float* __restrict__ R_U,
                      const float* __restrict__ alpha,
                      const float* __restrict__ beta,
                      const float* __restrict__ lambdas,
                      float* __restrict__ out)
{
    extern __shared__ __align__(16) float smem[];
    float* Fs  = smem;                                      // [CHK][FPAD] fp32
    ull*   Fbs = (ull*)(smem + FB_OFF);                     // [CHK][32] bf16-packed
    const int w = threadIdx.x >> 5;
    const int l = threadIdx.x & 31;
    float* CwA = smem + CS_OFF + w*512;                     // [kp][8]: c(2kp,0..2), c(2kp+1,0..2), pad2
    float* CwB = CwA + 256;
    float2* GwA = (float2*)(smem + GB_OFF + w*768);         // [j][h] (gV,gA)
    float2* GwB = GwA + 192;
    float*  Ws  = smem + WV_OFF + w*384;                    // [lane][12] -wv stash

    const int sA = blockIdx.x * (WARPS*2) + w*2;
    const int sB = sA + 1;
    const int k0 = l, k1 = l + 32;
    const int kpw = l >> 1;                 // C slot for k0
    const int cof = (l & 1) * 3;

    const float l1 = lambdas[0], l2 = lambdas[1];
    const float aaA = alpha[sA], bbA = beta[sA];
    const float aaB = alpha[sB], bbB = beta[sB];

    // ---- init: (c, wv_raw) pair-packed over interleaved PT ----
    {
        ull accw[2][2][3] = {{{0,0,0},{0,0,0}},{{0,0,0},{0,0,0}}};
        const ulonglong2* pt0 = (const ulonglong2*)(g_PT + k0*(2*HN));
        const ulonglong2* pt1 = (const ulonglong2*)(g_PT + k1*(2*HN));
        const float4* rpA = (const float4*)(R_U + (size_t)sA * (HN*3));
        const float4* rpB = (const float4*)(R_U + (size_t)sB * (HN*3));
        #pragma unroll 1
        for (int q = 0; q < HN/4; q++) {
            ulonglong2 pA0 = pt0[2*q], pA1 = pt0[2*q+1];
            ulonglong2 pB0 = pt1[2*q], pB1 = pt1[2*q+1];
            #pragma unroll
            for (int s = 0; s < 2; s++) {
                const float4* rp = s ? rpB : rpA;
                float4 r0 = rp[3*q], r1 = rp[3*q+1], r2 = rp[3*q+2];
                ull d0[3] = {fdup(r0.x), fdup(r0.y), fdup(r0.z)};
                ull d1[3] = {fdup(r0.w), fdup(r1.x), fdup(r1.y)};
                ull d2[3] = {fdup(r1.z), fdup(r1.w), fdup(r2.x)};
                ull d3[3] = {fdup(r2.y), fdup(r2.z), fdup(r2.w)};
                #pragma unroll
                for (int j = 0; j < 3; j++) {
                    accw[s][0][j] = ffma2(pA0.x, d0[j], accw[s][0][j]);
                    accw[s][0][j] = ffma2(pA0.y, d1[j], accw[s][0][j]);
                    accw[s][0][j] = ffma2(pA1.x, d2[j], accw[s][0][j]);
                    accw[s][0][j] = ffma2(pA1.y, d3[j], accw[s][0][j]);
                    accw[s][1][j] = ffma2(pB0.x, d0[j], accw[s][1][j]);
                    accw[s][1][j] = ffma2(pB0.y, d1[j], accw[s][1][j]);
                    accw[s][1][j] = ffma2(pB1.x, d2[j], accw[s][1][j]);
                    accw[s][1][j] = ffma2(pB1.y, d3[j], accw[s][1][j]);
                }
            }
        }
        #pragma unroll
        for (int s = 0; s < 2; s++) {
            float* Cw = s ? CwB : CwA;
            #pragma unroll
            for (int k = 0; k < 2; k++) {
                int slot = (kpw + (k ? 16 : 0))*8 + cof;
                #pragma unroll
                for (int j = 0; j < 3; j++) {
                    float cv, wvr;
                    funpack(accw[s][k][j], cv, wvr);
                    Cw[slot + j] = cv;
                    Ws[l*12 + s*6 + k*3 + j] = -2.f*l1*wvr;
                }
            }
        }
        __syncwarp();
    }

    for (int step = 0; step < 3; step++) {
        ull acc[2][2][3];   // packed (sum x*gV, sum y*gA); lo initialized to -wv
        #pragma unroll
        for (int s = 0; s < 2; s++)
            #pragma unroll
            for (int k = 0; k < 2; k++)
                #pragma unroll
                for (int j = 0; j < 3; j++)
                    acc[s][k][j] = pack2(Ws[l*12 + s*6 + k*3 + j], 0.f);

        for (int ch = 0; ch < NCHUNK; ch++) {
            const int base = ch * CHK;
            __syncthreads();   // previous chunk fully consumed by all warps
            {  // stage fp32 chunk
                const float4* src = (const float4*)(g_F2 + base*(2*KN));
                int t = threadIdx.x;
                #pragma unroll
                for (int i = 0; i < (CHK*2*KN/4)/256; i++) {
                    int idx = t + 256*i;
                    int h = idx >> 5, q = idx & 31;
                    ((float4*)(Fs + h*FPAD))[q] = src[h*32 + q];
                }
                // stage bf16 chunk (16 KB)
                const float4* srcb = (const float4*)(g_Fb + base*32);
                float4* dstb = (float4*)Fbs;
                #pragma unroll
                for (int i = 0; i < 4; i++)
                    dstb[t + 256*i] = srcb[t + 256*i];
            }
            __syncthreads();

            // ---- Phase A: forward (V,A) for 2 samples + elementwise grads ----
            {
                const ulonglong2* f0 = (const ulonglong2*)(Fs + l*FPAD);
                const ulonglong2* f1 = (const ulonglong2*)(Fs + (l+32)*FPAD);
                ull va[2][2][3] = {{{0,0,0},{0,0,0}},{{0,0,0},{0,0,0}}};
                #pragma unroll 2
                for (int kp = 0; kp < 32; kp++) {
                    ulonglong2 x0 = f0[kp], x1 = f1[kp];   // rows shared by both samples
                    {
                        float4 qa = *(const float4*)(CwA + 8*kp);
                        float2 ra = *(const float2*)(CwA + 8*kp + 4);
                        ull d0 = fdup(qa.x), d1 = fdup(qa.y), d2 = fdup(qa.z);
                        ull d3 = fdup(qa.w), d4 = fdup(ra.x), d5 = fdup(ra.y);
                        va[0][0][0] = ffma2(x0.x, d0, va[0][0][0]);
                        va[0][0][1] = ffma2(x0.x, d1, va[0][0][1]);
                        va[0][0][2] = ffma2(x0.x, d2, va[0][0][2]);
                        va[0][0][0] = ffma2(x0.y, d3, va[0][0][0]);
                        va[0][0][1] = ffma2(x0.y, d4, va[0][0][1]);
                        va[0][0][2] = ffma2(x0.y, d5, va[0][0][2]);
                        va[0][1][0] = ffma2(x1.x, d0, va[0][1][0]);
                        va[0][1][1] = ffma2(x1.x, d1, va[0][1][1]);
                        va[0][1][2] = ffma2(x1.x, d2, va[0][1][2]);
                        va[0][1][0] = ffma2(x1.y, d3, va[0][1][0]);
                        va[0][1][1] = ffma2(x1.y, d4, va[0][1][1]);
                        va[0][1][2] = ffma2(x1.y, d5, va[0][1][2]);
                    }
                    {
                        float4 qb = *(const float4*)(CwB + 8*kp);
                        float2 rb = *(const float2*)(CwB + 8*kp + 4);
                        ull d0 = fdup(qb.x), d1 = fdup(qb.y), d2 = fdup(qb.z);
                        ull d3 = fdup(qb.w), d4 = fdup(rb.x), d5 = fdup(rb.y);
                        va[1][0][0] = ffma2(x0.x, d0, va[1][0][0]);
                        va[1][0][1] = ffma2(x0.x, d1, va[1][0][1]);
                        va[1][0][2] = ffma2(x0.x, d2, va[1][0][2]);
                        va[1][0][0] = ffma2(x0.y, d3, va[1][0][0]);
                        va[1][0][1] = ffma2(x0.y, d4, va[1][0][1]);
                        va[1][0][2] = ffma2(x0.y, d5, va[1][0][2]);
                        va[1][1][0] = ffma2(x1.x, d0, va[1][1][0]);
                        va[1][1][1] = ffma2(x1.x, d1, va[1][1][1]);
                        va[1][1][2] = ffma2(x1.x, d2, va[1][1][2]);
                        va[1][1][0] = ffma2(x1.y, d3, va[1][1][0]);
                        va[1][1][1] = ffma2(x1.y, d4, va[1][1][1]);
                        va[1][1][2] = ffma2(x1.y, d5, va[1][1][2]);
                    }
                }
                float V[3], A[3], g[6];
                #pragma unroll
                for (int s = 0; s < 2; s++) {
                    float2* Gw = s ? GwB : GwA;
                    float aa = s ? aaB : aaA;
                    float bb = s ? bbB : bbA;
                    #pragma unroll
                    for (int r = 0; r < 2; r++) {
                        funpack(va[s][r][0], V[0], A[0]);
                        funpack(va[s][r][1], V[1], A[1]);
                        funpack(va[s][r][2], V[2], A[2]);
                        elemgrad(V[0],V[1],V[2], A[0],A[1],A[2], aa,bb,l2, g);
                        int hh = l + 32*r;
                        #pragma unroll
                        for (int j = 0; j < 3; j++)
                            Gw[j*CHK + hh] = make_float2(g[j], g[3+j]);
                    }
                }
            }
            __syncwarp();

            // ---- Phase B: dC accumulation via bf16 F (rows shared by samples) ----
            {
                const ulonglong2* pgA0 = (const ulonglong2*)(GwA);
                const ulonglong2* pgA1 = (const ulonglong2*)(GwA + CHK);
                const ulonglong2* pgA2 = (const ulonglong2*)(GwA + 2*CHK);
                const ulonglong2* pgB0 = (const ulonglong2*)(GwB);
                const ulonglong2* pgB1 = (const ulonglong2*)(GwB + CHK);
                const ulonglong2* pgB2 = (const ulonglong2*)(GwB + 2*CHK);
                #pragma unroll 2
                for (int hp = 0; hp < 32; hp++) {
                    ull w0 = Fbs[(2*hp)*32 + l];
                    ull w1 = Fbs[(2*hp+1)*32 + l];
                    ull t00 = bf2f2((unsigned)w0);
                    ull t01 = bf2f2((unsigned)(w0 >> 32));
                    ull t10 = bf2f2((unsigned)w1);
                    ull t11 = bf2f2((unsigned)(w1 >> 32));
                    ulonglong2 p0 = pgA0[hp], p1 = pgA1[hp], p2 = pgA2[hp];
                    acc[0][0][0] = ffma2(t00, p0.x, acc[0][0][0]);
                    acc[0][0][1] = ffma2(t00, p1.x, acc[0][0][1]);
                    acc[0][0][2] = ffma2(t00, p2.x, acc[0][0][2]);
                    acc[0][1][0] = ffma2(t01, p0.x, acc[0][1][0]);
                    acc[0][1][1] = ffma2(t01, p1.x, acc[0][1][1]);
                    acc[0][1][2] = ffma2(t01, p2.x, acc[0][1][2]);
                    acc[0][0][0] = ffma2(t10, p0.y, acc[0][0][0]);
                    acc[0][0][1] = ffma2(t10, p1.y, acc[0][0][1]);
                    acc[0][0][2] = ffma2(t10, p2.y, acc[0][0][2]);
                    acc[0][1][0] = ffma2(t11, p0.y, acc[0][1][0]);
                    acc[0][1][1] = ffma2(t11, p1.y, acc[0][1][1]);
                    acc[0][1][2] = ffma2(t11, p2.y, acc[0][1][2]);
                    ulonglong2 q0 = pgB0[hp], q1 = pgB1[hp], q2 = pgB2[hp];
                    acc[1][0][0] = ffma2(t00, q0.x, acc[1][0][0]);
                    acc[1][0][1] = ffma2(t00, q1.x, acc[1][0][1]);
                    acc[1][0][2] = ffma2(t00, q2.x, acc[1][0][2]);
                    acc[1][1][0] = ffma2(t01, q0.x, acc[1][1][0]);
                    acc[1][1][1] = ffma2(t01, q1.x, acc[1][1][1]);
                    acc[1][1][2] = ffma2(t01, q2.x, acc[1][1][2]);
                    acc[1][0][0] = ffma2(t10, q0.y, acc[1][0][0]);
                    acc[1][0][1] = ffma2(t10, q1.y, acc[1][0][1]);
                    acc[1][0][2] = ffma2(t10, q2.y, acc[1][0][2]);
                    acc[1][1][0] = ffma2(t11, q0.y, acc[1][1][0]);
                    acc[1][1][1] = ffma2(t11, q1.y, acc[1][1][1]);
                    acc[1][1][2] = ffma2(t11, q2.y, acc[1][1][2]);
                }
            }
        }

        // ---- Phase C: mc = M @ C for both samples, then SGD update ----
        ull mca[2][3] = {{0,0,0},{0,0,0}};
        {
            #pragma unroll 2
            for (int kp = 0; kp < 32; kp++) {
                ull pm0 = *(const ull*)&g_Mp[(2*kp)*32 + l];
                ull pm1 = *(const ull*)&g_Mp[(2*kp+1)*32 + l];
                {
                    float4 qa = *(const float4*)(CwA + 8*kp);
                    float2 ra = *(const float2*)(CwA + 8*kp + 4);
                    mca[0][0] = ffma2(pm0, fdup(qa.x), mca[0][0]);
                    mca[0][1] = ffma2(pm0, fdup(qa.y), mca[0][1]);
                    mca[0][2] = ffma2(pm0, fdup(qa.z), mca[0][2]);
                    mca[0][0] = ffma2(pm1, fdup(qa.w), mca[0][0]);
                    mca[0][1] = ffma2(pm1, fdup(ra.x), mca[0][1]);
                    mca[0][2] = ffma2(pm1, fdup(ra.y), mca[0][2]);
                }
                {
                    float4 qb = *(const float4*)(CwB + 8*kp);
                    float2 rb = *(const float2*)(CwB + 8*kp + 4);
                    mca[1][0] = ffma2(pm0, fdup(qb.x), mca[1][0]);
                    mca[1][1] = ffma2(pm0, fdup(qb.y), mca[1][1]);
                    mca[1][2] = ffma2(pm0, fdup(qb.z), mca[1][2]);
                    mca[1][0] = ffma2(pm1, fdup(qb.w), mca[1][0]);
                    mca[1][1] = ffma2(pm1, fdup(rb.x), mca[1][1]);
                    mca[1][2] = ffma2(pm1, fdup(rb.y), mca[1][2]);
                }
            }
        }
        __syncwarp();   // all lanes done reading Cw before update
        #pragma unroll
        for (int s = 0; s < 2; s++) {
            float* Cw = s ? CwB : CwA;
            #pragma unroll
            for (int k = 0; k < 2; k++) {
                int slot = (kpw + (k ? 16 : 0))*8 + cof;
                #pragma unroll
                for (int j = 0; j < 3; j++) {
                    float dlo, dhi, m0, m1;
                    funpack(acc[s][k][j], dlo, dhi);    // dlo includes -wv
                    funpack(mca[s][j], m0, m1);
                    float m = k ? m1 : m0;
                    float cold = Cw[slot + j];
                    Cw[slot + j] = cold - LRATE * (dlo + dhi + m);
                }
            }
        }
        __syncwarp();
    }

    // ---- output ----
    #pragma unroll
    for (int s = 0; s < 2; s++) {
        float* op = out + (size_t)(sA + s) * (KN*3);
        float* Cw = s ? CwB : CwA;
        #pragma unroll
        for (int k = 0; k < 2; k++) {
            int kidx = k ? k1 : k0;
            int slot = (kpw + (k ? 16 : 0))*8 + cof;
            #pragma unroll
            for (int j = 0; j < 3; j++)
                op[kidx*3 + j] = Cw[slot + j];
        }
    }
}

extern "C" void kernel_launch(void* const* d_in, const int* in_sizes, int n_in,
                              void* d_out, int out_size)
{
    const float* R_U     = (const float*)d_in[0];
    const float* alpha   = (const float*)d_in[1];
    const float* beta    = (const float*)d_in[2];
    const float* lambdas = (const float*)d_in[3];
    const float* B       = (const float*)d_in[4];
    const float* Bd      = (const float*)d_in[5];
    const float* Bdd     = (const float*)d_in[6];
    const float* Bddd    = (const float*)d_in[7];
    const float* Bpinv   = (const float*)d_in[8];

    cudaFuncSetAttribute(inner_opt_kernel,
                         cudaFuncAttributeMaxDynamicSharedMemorySize, SMEM_BYTES);

    prep_kernel<<<192, 256>>>(B, Bd, Bdd, Bddd, Bpinv, lambdas);
    inner_opt_kernel<<<NSAMP/(WARPS*2), 256, SMEM_BYTES>>>(
        R_U, alpha, beta, lambdas, (float*)d_out);
}

// round 5
// speedup vs baseline: 4.9118x; 1.0352x over previous
#include <cuda_runtime.h>
#include <cuda_fp16.h>

typedef unsigned long long ull;

#define HN 512
#define KN 64
#define NSAMP 16384
#define LRATE 0.001f
#define EPSF 1e-8f
#define WARPS 8
#define CHK 64
#define NCHUNK (HN/CHK)
#define FH_H2 68                      // half2 per staged row (272 B); 68%32==4 -> conflict-free LDS.128

// smem layout (float units; half2 == 4B == 1 unit)
#define FS_FLOATS   (CHK*FH_H2)       // 4352
#define CS_OFF      FS_FLOATS
#define CS_WARP     576               // 16 quads * 36 floats (A at +0, B at +16, pad)
#define GB_OFF      (CS_OFF + WARPS*CS_WARP)
#define GB_WARP     768
#define WV_OFF      (GB_OFF + WARPS*GB_WARP)
#define SMEM_FLOATS (WV_OFF + WARPS*384)
#define SMEM_BYTES  (SMEM_FLOATS*4)   // 72704 B -> 2 CTAs/SM

__device__ __align__(16) unsigned g_Fh[HN*KN];   // [h][k] = half2(Bd, Bdd)
__device__ __align__(16) float  g_PT[KN*2*HN];   // [k][2h] = (Bpinv[k][h], B[h][k])
__device__ __align__(16) float2 g_Mp[KN*32];     // [kk*32+l] = (M[kk][l], M[kk][l+32])

// ---- packed f32x2 helpers ----
__device__ __forceinline__ ull ffma2(ull a, ull b, ull c){
    ull d; asm("fma.rn.f32x2 %0,%1,%2,%3;" : "=l"(d) : "l"(a), "l"(b), "l"(c)); return d;
}
__device__ __forceinline__ void funpack(ull u, float& x, float& y){
    asm("mov.b64 {%0,%1},%2;" : "=f"(x), "=f"(y) : "l"(u));
}
__device__ __forceinline__ ull fdup(float x){
    ull r; asm("mov.b64 %0,{%1,%1};" : "=l"(r) : "f"(x)); return r;
}
__device__ __forceinline__ ull pack2(float lo, float hi){
    ull r; asm("mov.b64 %0,{%1,%2};" : "=l"(r) : "f"(lo), "f"(hi)); return r;
}
// half2 bits -> packed f32x2
__device__ __forceinline__ ull h2f2(unsigned u){
    __half2 h = *(__half2*)&u;
    float2 f = __half22float2(h);
    return pack2(f.x, f.y);
}

// K1: prep (blocks 0..127) + gram (blocks 128..191)
__global__ void prep_kernel(const float* __restrict__ B,
                            const float* __restrict__ Bd,
                            const float* __restrict__ Bdd,
                            const float* __restrict__ Bddd,
                            const float* __restrict__ Bpinv,
                            const float* __restrict__ lambdas)
{
    int bid = blockIdx.x, t = threadIdx.x;
    if (bid < 128) {
        int idx = bid*256 + t;
        // fp16 tile: idx -> (h,k)
        __half2 hv = __halves2half2(__float2half(Bd[idx]), __float2half(Bdd[idx]));
        g_Fh[idx] = *(unsigned*)&hv;
        // PT interleave: idx -> (k2,h2)
        int k2 = idx >> 9, h2 = idx & (HN-1);
        g_PT[k2*(2*HN) + 2*h2]     = Bpinv[idx];
        g_PT[k2*(2*HN) + 2*h2 + 1] = B[h2*KN + k2];
    } else {
        __shared__ float pab[4][KN], paj[4][KN], Mrow[KN];
        int kk = bid - 128;
        int k2 = t & 63, part = t >> 6;
        float ab = 0.f, aj = 0.f;
        for (int h = part*128; h < part*128 + 128; h++) {
            ab += B[h*KN + kk]    * B[h*KN + k2];
            aj += Bddd[h*KN + kk] * Bddd[h*KN + k2];
        }
        pab[part][k2] = ab; paj[part][k2] = aj;
        __syncthreads();
        if (t < KN) {
            float sab = pab[0][t]+pab[1][t]+pab[2][t]+pab[3][t];
            float saj = paj[0][t]+paj[1][t]+paj[2][t]+paj[3][t];
            Mrow[t] = 2.f * (lambdas[0]*sab + lambdas[2]*saj);
        }
        __syncthreads();
        if (t < 32) g_Mp[kk*32 + t] = make_float2(Mrow[t], Mrow[t+32]);
    }
}

// Elementwise gradient of the power-law term wrt V and A (includes l2).
__device__ __forceinline__ void elemgrad(
    float v0, float v1, float v2,
    float a0, float a1, float a2,
    float aa, float bb, float l2, float* g)
{
    float vsq = v0*v0 + v1*v1 + v2*v2;
    float inv_vn = vsq > 0.f ? rsqrtf(vsq) : 0.f;
    float vn  = vsq * inv_vn;
    float vne = vn + EPSF;

    float cx = v1*a2 - v2*a1;
    float cy = v2*a0 - v0*a2;
    float cz = v0*a1 - v1*a0;
    float csq = cx*cx + cy*cy + cz*cz;
    float inv_cn = csq > 0.f ? rsqrtf(csq) : 0.f;
    float cn = csq * inv_cn;

    float den = vne*vne*vne + EPSF;
    float inv_den = __fdividef(1.f, den);
    float kappa = cn * inv_den;

    float ks  = fminf(fmaxf(kappa, 1e-4f), 1e4f);
    float lpr = bb * __logf(ks);
    float lp  = fminf(fmaxf(lpr, -10.f), 10.f);
    float traw   = aa * __expf(lp);
    float target = fminf(fmaxf(traw, 1e-6f), 1e6f);

    float u   = vn - target;
    float gvn = 2.f * l2 * u;
    float gt  = (traw > 1e-6f && traw < 1e6f) ? (-2.f * l2 * u) : 0.f;
    float glk = ((lpr > -10.f && lpr < 10.f) ? gt * traw : 0.f) * bb;
    float gk  = (kappa > 1e-4f && kappa < 1e4f) ? glk : 0.f;
    float gcn  = gk * inv_cn;
    float gden = -gk * inv_den;
    gvn += gden * 3.f * vne * vne;

    float scr = gcn * inv_cn;
    float gc0 = scr * cx, gc1 = scr * cy, gc2 = scr * cz;
    float sV = gvn * inv_vn;
    g[0] = sV*v0 + a1*gc2 - a2*gc1;
    g[1] = sV*v1 + a2*gc0 - a0*gc2;
    g[2] = sV*v2 + a0*gc1 - a1*gc0;
    g[3] = gc1*v2 - gc2*v1;
    g[4] = gc2*v0 - gc0*v2;
    g[5] = gc0*v1 - gc1*v0;
}

// K2: main. One warp = 2 samples; one fp16 tile serves forward rows + backward columns.
__global__ __launch_bounds__(256, 2)
void inner_opt_kernel(const float* __restrict__ R_U,
                      const float* __restrict__ alpha,
                      const float* __restrict__ beta,
                      const float* __restrict__ lambdas,
                      float* __restrict__ out)
{
    extern __shared__ __align__(16) float smem[];
    char* Fh = (char*)smem;                                 // [CHK] rows of 272 B (68 half2)
    const int w = threadIdx.x >> 5;
    const int l = threadIdx.x & 31;
    float* Cq  = smem + CS_OFF + w*CS_WARP;                 // [quad][36]: A 12f @+0, B 12f @+16
    float2* GwA = (float2*)(smem + GB_OFF + w*GB_WARP);     // [j][h] (gV,gA)
    float2* GwB = GwA + 192;
    float*  Ws  = smem + WV_OFF + w*384;                    // [lane][12] -wv stash

    const int sA = blockIdx.x * (WARPS*2) + w*2;
    const int sB = sA + 1;
    const int k0 = l, k1 = l + 32;
    const int qa = l >> 2, la3 = (l & 3) * 3;               // C slot coords for k0 (k1: quad+8)

    const float l1 = lambdas[0], l2 = lambdas[1];
    const float aaA = alpha[sA], bbA = beta[sA];
    const float aaB = alpha[sB], bbB = beta[sB];

    float c[2][2][3];   // [sample][k-half][j] kept in registers across all steps

    // ---- init: (c, wv_raw) pair-packed over interleaved PT ----
    {
        ull accw[2][2][3] = {{{0,0,0},{0,0,0}},{{0,0,0},{0,0,0}}};
        const ulonglong2* pt0 = (const ulonglong2*)(g_PT + k0*(2*HN));
        const ulonglong2* pt1 = (const ulonglong2*)(g_PT + k1*(2*HN));
        const float4* rpA = (const float4*)(R_U + (size_t)sA * (HN*3));
        const float4* rpB = (const float4*)(R_U + (size_t)sB * (HN*3));
        #pragma unroll 1
        for (int q = 0; q < HN/4; q++) {
            ulonglong2 pA0 = pt0[2*q], pA1 = pt0[2*q+1];
            ulonglong2 pB0 = pt1[2*q], pB1 = pt1[2*q+1];
            #pragma unroll
            for (int s = 0; s < 2; s++) {
                const float4* rp = s ? rpB : rpA;
                float4 r0 = rp[3*q], r1 = rp[3*q+1], r2 = rp[3*q+2];
                ull d0[3] = {fdup(r0.x), fdup(r0.y), fdup(r0.z)};
                ull d1[3] = {fdup(r0.w), fdup(r1.x), fdup(r1.y)};
                ull d2[3] = {fdup(r1.z), fdup(r1.w), fdup(r2.x)};
                ull d3[3] = {fdup(r2.y), fdup(r2.z), fdup(r2.w)};
                #pragma unroll
                for (int j = 0; j < 3; j++) {
                    accw[s][0][j] = ffma2(pA0.x, d0[j], accw[s][0][j]);
                    accw[s][0][j] = ffma2(pA0.y, d1[j], accw[s][0][j]);
                    accw[s][0][j] = ffma2(pA1.x, d2[j], accw[s][0][j]);
                    accw[s][0][j] = ffma2(pA1.y, d3[j], accw[s][0][j]);
                    accw[s][1][j] = ffma2(pB0.x, d0[j], accw[s][1][j]);
                    accw[s][1][j] = ffma2(pB0.y, d1[j], accw[s][1][j]);
                    accw[s][1][j] = ffma2(pB1.x, d2[j], accw[s][1][j]);
                    accw[s][1][j] = ffma2(pB1.y, d3[j], accw[s][1][j]);
                }
            }
        }
        #pragma unroll
        for (int s = 0; s < 2; s++)
            #pragma unroll
            for (int k = 0; k < 2; k++) {
                int slot = (qa + (k ? 8 : 0))*36 + s*16 + la3;
                #pragma unroll
                for (int j = 0; j < 3; j++) {
                    float cv, wvr;
                    funpack(accw[s][k][j], cv, wvr);
                    c[s][k][j] = cv;
                    Cq[slot + j] = cv;
                    Ws[l*12 + s*6 + k*3 + j] = -2.f*l1*wvr;
                }
            }
        __syncwarp();
    }

    for (int step = 0; step < 3; step++) {
        ull acc[2][2][3];   // packed (sum x*gV, sum y*gA); lo initialized to -wv
        #pragma unroll
        for (int s = 0; s < 2; s++)
            #pragma unroll
            for (int k = 0; k < 2; k++)
                #pragma unroll
                for (int j = 0; j < 3; j++)
                    acc[s][k][j] = pack2(Ws[l*12 + s*6 + k*3 + j], 0.f);

        for (int ch = 0; ch < NCHUNK; ch++) {
            const int base = ch * CHK;
            __syncthreads();   // previous chunk fully consumed by all warps
            {  // stage fp16 tile (16 KB) into padded rows
                const float4* src = (const float4*)(g_Fh + base*KN);
                int t = threadIdx.x;
                #pragma unroll
                for (int i = 0; i < 4; i++) {
                    int idx = t + 256*i;
                    int h = idx >> 4, q = idx & 15;
                    *(float4*)(Fh + h*272 + q*16) = src[idx];
                }
            }
            __syncthreads();

            // ---- Phase A: forward (V,A) for 2 samples + elementwise grads ----
            {
                const char* r0 = Fh + l*272;
                const char* r1 = Fh + (l+32)*272;
                ull va[2][2][3] = {{{0,0,0},{0,0,0}},{{0,0,0},{0,0,0}}};
                #pragma unroll 2
                for (int q = 0; q < 16; q++) {
                    ulonglong2 u0 = *(const ulonglong2*)(r0 + q*16);
                    ulonglong2 u1 = *(const ulonglong2*)(r1 + q*16);
                    ull x0[4], x1[4];
                    x0[0] = h2f2((unsigned)u0.x); x0[1] = h2f2((unsigned)(u0.x >> 32));
                    x0[2] = h2f2((unsigned)u0.y); x0[3] = h2f2((unsigned)(u0.y >> 32));
                    x1[0] = h2f2((unsigned)u1.x); x1[1] = h2f2((unsigned)(u1.x >> 32));
                    x1[2] = h2f2((unsigned)u1.y); x1[3] = h2f2((unsigned)(u1.y >> 32));
                    const float* cqp = Cq + q*36;
                    #pragma unroll
                    for (int s = 0; s < 2; s++) {
                        float4 c0 = *(const float4*)(cqp + s*16);
                        float4 c1 = *(const float4*)(cqp + s*16 + 4);
                        float4 c2 = *(const float4*)(cqp + s*16 + 8);
                        float cf[12] = {c0.x,c0.y,c0.z,c0.w,
                                        c1.x,c1.y,c1.z,c1.w,
                                        c2.x,c2.y,c2.z,c2.w};
                        #pragma unroll
                        for (int i = 0; i < 4; i++) {
                            ull d0 = fdup(cf[i*3+0]);
                            ull d1 = fdup(cf[i*3+1]);
                            ull d2 = fdup(cf[i*3+2]);
                            va[s][0][0] = ffma2(x0[i], d0, va[s][0][0]);
                            va[s][0][1] = ffma2(x0[i], d1, va[s][0][1]);
                            va[s][0][2] = ffma2(x0[i], d2, va[s][0][2]);
                            va[s][1][0] = ffma2(x1[i], d0, va[s][1][0]);
                            va[s][1][1] = ffma2(x1[i], d1, va[s][1][1]);
                            va[s][1][2] = ffma2(x1[i], d2, va[s][1][2]);
                        }
                    }
                }
                float V[3], A[3], g[6];
                #pragma unroll
                for (int s = 0; s < 2; s++) {
                    float2* Gw = s ? GwB : GwA;
                    float aa = s ? aaB : aaA;
                    float bb = s ? bbB : bbA;
                    #pragma unroll
                    for (int r = 0; r < 2; r++) {
                        funpack(va[s][r][0], V[0], A[0]);
                        funpack(va[s][r][1], V[1], A[1]);
                        funpack(va[s][r][2], V[2], A[2]);
                        elemgrad(V[0],V[1],V[2], A[0],A[1],A[2], aa,bb,l2, g);
                        int hh = l + 32*r;
                        #pragma unroll
                        for (int j = 0; j < 3; j++)
                            Gw[j*CHK + hh] = make_float2(g[j], g[3+j]);
                    }
                }
            }
            __syncwarp();

            // ---- Phase B: dC accumulation (fp16 column reads of the same tile) ----
            {
                const ulonglong2* pgA0 = (const ulonglong2*)(GwA);
                const ulonglong2* pgA1 = (const ulonglong2*)(GwA + CHK);
                const ulonglong2* pgA2 = (const ulonglong2*)(GwA + 2*CHK);
                const ulonglong2* pgB0 = (const ulonglong2*)(GwB);
                const ulonglong2* pgB1 = (const ulonglong2*)(GwB + CHK);
                const ulonglong2* pgB2 = (const ulonglong2*)(GwB + 2*CHK);
                #pragma unroll 2
                for (int hp = 0; hp < 32; hp++) {
                    const char* rowA = Fh + (2*hp)*272;
                    const char* rowB = Fh + (2*hp+1)*272;
                    ull t00 = h2f2(*(const unsigned*)(rowA + l*4));
                    ull t01 = h2f2(*(const unsigned*)(rowA + (l+32)*4));
                    ull t10 = h2f2(*(const unsigned*)(rowB + l*4));
                    ull t11 = h2f2(*(const unsigned*)(rowB + (l+32)*4));
                    ulonglong2 p0 = pgA0[hp], p1 = pgA1[hp], p2 = pgA2[hp];
                    acc[0][0][0] = ffma2(t00, p0.x, acc[0][0][0]);
                    acc[0][0][1] = ffma2(t00, p1.x, acc[0][0][1]);
                    acc[0][0][2] = ffma2(t00, p2.x, acc[0][0][2]);
                    acc[0][1][0] = ffma2(t01, p0.x, acc[0][1][0]);
                    acc[0][1][1] = ffma2(t01, p1.x, acc[0][1][1]);
                    acc[0][1][2] = ffma2(t01, p2.x, acc[0][1][2]);
                    acc[0][0][0] = ffma2(t10, p0.y, acc[0][0][0]);
                    acc[0][0][1] = ffma2(t10, p1.y, acc[0][0][1]);
                    acc[0][0][2] = ffma2(t10, p2.y, acc[0][0][2]);
                    acc[0][1][0] = ffma2(t11, p0.y, acc[0][1][0]);
                    acc[0][1][1] = ffma2(t11, p1.y, acc[0][1][1]);
                    acc[0][1][2] = ffma2(t11, p2.y, acc[0][1][2]);
                    ulonglong2 q0 = pgB0[hp], q1 = pgB1[hp], q2 = pgB2[hp];
                    acc[1][0][0] = ffma2(t00, q0.x, acc[1][0][0]);
                    acc[1][0][1] = ffma2(t00, q1.x, acc[1][0][1]);
                    acc[1][0][2] = ffma2(t00, q2.x, acc[1][0][2]);
                    acc[1][1][0] = ffma2(t01, q0.x, acc[1][1][0]);
                    acc[1][1][1] = ffma2(t01, q1.x, acc[1][1][1]);
                    acc[1][1][2] = ffma2(t01, q2.x, acc[1][1][2]);
                    acc[1][0][0] = ffma2(t10, q0.y, acc[1][0][0]);
                    acc[1][0][1] = ffma2(t10, q1.y, acc[1][0][1]);
                    acc[1][0][2] = ffma2(t10, q2.y, acc[1][0][2]);
                    acc[1][1][0] = ffma2(t11, q0.y, acc[1][1][0]);
                    acc[1][1][1] = ffma2(t11, q1.y, acc[1][1][1]);
                    acc[1][1][2] = ffma2(t11, q2.y, acc[1][1][2]);
                }
            }
        }

        // ---- Phase C: mc = M @ C for both samples, then SGD update ----
        ull mca[2][3] = {{0,0,0},{0,0,0}};
        {
            #pragma unroll 2
            for (int q = 0; q < 16; q++) {
                const float* cqp = Cq + q*36;
                float4 a0 = *(const float4*)(cqp);
                float4 a1 = *(const float4*)(cqp + 4);
                float4 a2 = *(const float4*)(cqp + 8);
                float4 b0 = *(const float4*)(cqp + 16);
                float4 b1 = *(const float4*)(cqp + 20);
                float4 b2 = *(const float4*)(cqp + 24);
                float cA[12] = {a0.x,a0.y,a0.z,a0.w, a1.x,a1.y,a1.z,a1.w, a2.x,a2.y,a2.z,a2.w};
                float cB[12] = {b0.x,b0.y,b0.z,b0.w, b1.x,b1.y,b1.z,b1.w, b2.x,b2.y,b2.z,b2.w};
                #pragma unroll
                for (int i = 0; i < 4; i++) {
                    int kk = 4*q + i;
                    ull pm = *(const ull*)&g_Mp[kk*32 + l];
                    mca[0][0] = ffma2(pm, fdup(cA[i*3+0]), mca[0][0]);
                    mca[0][1] = ffma2(pm, fdup(cA[i*3+1]), mca[0][1]);
                    mca[0][2] = ffma2(pm, fdup(cA[i*3+2]), mca[0][2]);
                    mca[1][0] = ffma2(pm, fdup(cB[i*3+0]), mca[1][0]);
                    mca[1][1] = ffma2(pm, fdup(cB[i*3+1]), mca[1][1]);
                    mca[1][2] = ffma2(pm, fdup(cB[i*3+2]), mca[1][2]);
                }
            }
        }
        __syncwarp();   // all lanes done reading C before update
        #pragma unroll
        for (int s = 0; s < 2; s++)
            #pragma unroll
            for (int k = 0; k < 2; k++) {
                int slot = (qa + (k ? 8 : 0))*36 + s*16 + la3;
                #pragma unroll
                for (int j = 0; j < 3; j++) {
                    float dlo, dhi, m0, m1;
                    funpack(acc[s][k][j], dlo, dhi);    // dlo includes -wv
                    funpack(mca[s][j], m0, m1);
                    float m = k ? m1 : m0;
                    c[s][k][j] -= LRATE * (dlo + dhi + m);
                    Cq[slot + j] = c[s][k][j];
                }
            }
        __syncwarp();
    }

    // ---- output (from registers) ----
    #pragma unroll
    for (int s = 0; s < 2; s++) {
        float* op = out + (size_t)(sA + s) * (KN*3);
        #pragma unroll
        for (int j = 0; j < 3; j++) {
            op[k0*3 + j] = c[s][0][j];
            op[k1*3 + j] = c[s][1][j];
        }
    }
}

extern "C" void kernel_launch(void* const* d_in, const int* in_sizes, int n_in,
                              void* d_out, int out_size)
{
    const float* R_U     = (const float*)d_in[0];
    const float* alpha   = (const float*)d_in[1];
    const float* beta    = (const float*)d_in[2];
    const float* lambdas = (const float*)d_in[3];
    const float* B       = (const float*)d_in[4];
    const float* Bd      = (const float*)d_in[5];
    const float* Bdd     = (const float*)d_in[6];
    const float* Bddd    = (const float*)d_in[7];
    const float* Bpinv   = (const float*)d_in[8];

    cudaFuncSetAttribute(inner_opt_kernel,
                         cudaFuncAttributeMaxDynamicSharedMemorySize, SMEM_BYTES);

    prep_kernel<<<192, 256>>>(B, Bd, Bdd, Bddd, Bpinv, lambdas);
    inner_opt_kernel<<<NSAMP/(WARPS*2), 256, SMEM_BYTES>>>(
        R_U, alpha, beta, lambdas, (float*)d_out);
}